// round 7
// baseline (speedup 1.0000x reference)
#include <cuda_runtime.h>
#include <cuda_bf16.h>
#include <cstdint>

// Inputs (metadata order):
//   d_in[0]: output  float32  [16, 512, 32000]  (B*S = 8192 rows, V = 32000)
//   d_in[1]: target  int32    [16, 512]
// Output: scalar float32 = sum(target!=0 ? -log(p_target) : 0) / count(target!=0)
//
// Strategy: one cluster of 8 CTAs x 1024 threads = 8192 threads, 1 row each.
// Cross-CTA combine via DSMEM into CTA rank 0 (no global atomics, no
// persistent device state -> trivially graph-replayable).

#define ROWS     8192
#define VOCAB    32000
#define NCTAS    8
#define NTHREADS 1024
#define NWARPS   (NTHREADS / 32)   // 32

__global__ __launch_bounds__(NTHREADS, 1) __cluster_dims__(NCTAS, 1, 1)
void nll_gather_kernel(const float* __restrict__ out_probs,
                       const int* __restrict__ target,
                       float* __restrict__ result)
{
    __shared__ float2 s_part[NWARPS];     // per-warp partials
    __shared__ float2 s_cluster[NCTAS];   // per-CTA partials (used in rank 0)

    const int tid  = threadIdx.x;
    const int warp = tid >> 5;
    const int lane = tid & 31;

    uint32_t rank;
    asm("mov.u32 %0, %%cluster_ctarank;" : "=r"(rank));

    const int row = (int)rank * NTHREADS + tid;

    // Dependent chain: target load -> gather (2x memory latency, inherent)
    const int t = target[row];
    const float p = __ldcg(&out_probs[(size_t)row * VOCAB + t]);

    float lsum = (t != 0) ? -__logf(p) : 0.0f;
    float lcnt = (t != 0) ? 1.0f : 0.0f;

    // Warp shuffle reduction
    #pragma unroll
    for (int off = 16; off > 0; off >>= 1) {
        lsum += __shfl_down_sync(0xFFFFFFFFu, lsum, off);
        lcnt += __shfl_down_sync(0xFFFFFFFFu, lcnt, off);
    }
    if (lane == 0) s_part[warp] = make_float2(lsum, lcnt);
    __syncthreads();

    // Warp 0: reduce 32 warp-partials (one per lane), then DSMEM-store
    // this CTA's partial into rank 0's s_cluster[rank].
    if (warp == 0) {
        float2 v = s_part[lane];
        #pragma unroll
        for (int off = 16; off > 0; off >>= 1) {
            v.x += __shfl_down_sync(0xFFFFFFFFu, v.x, off);
            v.y += __shfl_down_sync(0xFFFFFFFFu, v.y, off);
        }
        if (lane == 0) {
            // local smem address of s_cluster[rank]
            uint32_t laddr;
            asm("{ .reg .u64 t; cvta.to.shared.u64 t, %1; cvt.u32.u64 %0, t; }"
                : "=r"(laddr) : "l"(&s_cluster[rank]));
            uint32_t raddr;
            asm("mapa.shared::cluster.u32 %0, %1, 0;" : "=r"(raddr) : "r"(laddr));
            asm volatile("st.shared::cluster.v2.f32 [%0], {%1, %2};"
                         :: "r"(raddr), "f"(v.x), "f"(v.y) : "memory");
        }
    }

    // All threads of all CTAs: cluster barrier (orders DSMEM stores).
    asm volatile("barrier.cluster.arrive.aligned;" ::: "memory");
    asm volatile("barrier.cluster.wait.aligned;"   ::: "memory");

    // Rank 0, warp 0 finalizes from its own smem.
    if (rank == 0 && warp == 0) {
        float2 f = (lane < NCTAS) ? s_cluster[lane] : make_float2(0.f, 0.f);
        #pragma unroll
        for (int off = NCTAS / 2; off > 0; off >>= 1) {
            f.x += __shfl_down_sync(0xFFFFFFFFu, f.x, off);
            f.y += __shfl_down_sync(0xFFFFFFFFu, f.y, off);
        }
        if (lane == 0) result[0] = f.x / f.y;
    }
}

extern "C" void kernel_launch(void* const* d_in, const int* in_sizes, int n_in,
                              void* d_out, int out_size)
{
    const float* probs  = (const float*)d_in[0];
    const int*   target = (const int*)d_in[1];
    float*       result = (float*)d_out;

    nll_gather_kernel<<<NCTAS, NTHREADS>>>(probs, target, result);
}

// round 8
// speedup vs baseline: 1.0386x; 1.0386x over previous
#include <cuda_runtime.h>
#include <cuda_bf16.h>
#include <cstdint>

// Inputs (metadata order):
//   d_in[0]: output  float32  [16, 512, 32000]  (B*S = 8192 rows, V = 32000)
//   d_in[1]: target  int32    [16, 512]
// Output: scalar float32 = sum(target!=0 ? -log(p_target) : 0) / count(target!=0)
//
// Cross-block combine: ONE u64 atomicAdd per block, packing
//   bits[58:63] arrival counter (+1<<58 per block)
//   bits[14:57] sum, fixed-point scale 2^24  (total < 2^41)
//   bits[ 0:13] count                         (total <= 8192)
// Integer adds are order-independent -> deterministic. The atomic's return
// value lets the last-arriving block finalize with NO memory reads.

#define ROWS     8192
#define VOCAB    32000
#define NBLOCKS  32
#define NTHREADS 256          // 1 row per thread
#define NWARPS   (NTHREADS / 32)

#define CTR_ONE   (1ULL << 58)
#define SUM_SHIFT 14
#define CNT_MASK  ((1ULL << SUM_SHIFT) - 1ULL)
#define SUM_MASK  ((1ULL << 58) - 1ULL)
#define FP_SCALE  16777216.0f          // 2^24

__device__ unsigned long long g_acc;   // zero-init; finalizer resets

__global__ __launch_bounds__(NTHREADS, 1)
void nll_gather_kernel(const float* __restrict__ out_probs,
                       const int* __restrict__ target,
                       float* __restrict__ result)
{
    const int tid = threadIdx.x;
    const int row = blockIdx.x * NTHREADS + tid;

    // Dependent chain: target load -> gather (2x memory latency, inherent)
    const int t = target[row];
    const float p = __ldcg(&out_probs[(size_t)row * VOCAB + t]);

    float lsum = (t != 0) ? -__logf(p) : 0.0f;
    float lcnt = (t != 0) ? 1.0f : 0.0f;

    // Warp shuffle reduction
    #pragma unroll
    for (int off = 16; off > 0; off >>= 1) {
        lsum += __shfl_down_sync(0xFFFFFFFFu, lsum, off);
        lcnt += __shfl_down_sync(0xFFFFFFFFu, lcnt, off);
    }

    __shared__ float2 s_part[NWARPS];
    const int warp = tid >> 5;
    const int lane = tid & 31;
    if (lane == 0) s_part[warp] = make_float2(lsum, lcnt);
    __syncthreads();

    if (warp == 0) {
        float2 v = (lane < NWARPS) ? s_part[lane] : make_float2(0.f, 0.f);
        #pragma unroll
        for (int off = NWARPS / 2; off > 0; off >>= 1) {
            v.x += __shfl_down_sync(0xFFFFFFFFu, v.x, off);
            v.y += __shfl_down_sync(0xFFFFFFFFu, v.y, off);
        }

        if (lane == 0) {
            // Pack this block's contribution.
            unsigned long long fx =
                (unsigned long long)(v.x * FP_SCALE + 0.5f);   // < 2^36
            unsigned long long pk =
                CTR_ONE | (fx << SUM_SHIFT) | (unsigned long long)(int)v.y;

            unsigned long long old = atomicAdd(&g_acc, pk);

            if ((old >> 58) == NBLOCKS - 1) {
                // Last arriver: total = old + own contribution. No loads.
                unsigned long long tot = old + pk;
                float sum = (float)((tot & SUM_MASK) >> SUM_SHIFT) *
                            (1.0f / FP_SCALE);
                float cnt = (float)(tot & CNT_MASK);
                result[0] = sum / cnt;
                g_acc = 0ULL;   // reset for next graph replay
            }
        }
    }
}

extern "C" void kernel_launch(void* const* d_in, const int* in_sizes, int n_in,
                              void* d_out, int out_size)
{
    const float* probs  = (const float*)d_in[0];
    const int*   target = (const int*)d_in[1];
    float*       result = (float*)d_out;

    nll_gather_kernel<<<NBLOCKS, NTHREADS>>>(probs, target, result);
}